// round 15
// baseline (speedup 1.0000x reference)
#include <cuda_runtime.h>
#include <cuda_fp16.h>
#include <cstdint>
#include <cstddef>

// ---------------------------------------------------------------------------
// Problem constants
// ---------------------------------------------------------------------------
#define Bb     8
#define Tt     2048
#define Mm     1024
#define PROWS  (Bb * Tt)      // 16384
#define CL     64             // scan chunk length
#define NC     (Tt / CL)      // 32 chunks
#define BM     (Bb * Mm)      // 8192

// ---------------------------------------------------------------------------
// Scratch (static __device__ arrays; runtime allocation is forbidden)
// ---------------------------------------------------------------------------
__device__ float  g_r [PROWS * Mm];   // sigmoid(x@wr^T + b)   (t-major, f32)
__device__ float  g_og[PROWS * Mm];   // sigmoid(x@wog^T + b)  (t-major, f32)
__device__ float  g_zi[PROWS * Mm];   // raw x@wi^T            (t-major, f32)
__device__ float  g_sg[PROWS * Mm];   // sigmoid(x@wig^T + b)  (t-major, f32)
__device__ __half g_y [PROWS * Mm];   // softsign(h)*og, p-major, fp16
__device__ __half g_xh[PROWS * Mm];   // x rounded to fp16 (rn)
__device__ __half g_w0[Mm * Mm];      // wr  fp16
__device__ __half g_w1[Mm * Mm];      // wog fp16
__device__ __half g_w2[Mm * Mm];      // wi  fp16
__device__ __half g_w3[Mm * Mm];      // wig fp16
__device__ __half g_w4[Mm * Mm];      // wo  fp16
__device__ float  g_cA[NC * BM];
__device__ float  g_cB[NC * BM];
__device__ float  g_h0[NC * BM];

// ---------------------------------------------------------------------------
// Helpers
// ---------------------------------------------------------------------------
__device__ __forceinline__ float sigmf(float x) {
    return 1.0f / (1.0f + __expf(-x));
}
__device__ __forceinline__ uint32_t smem_u32(const void* p) {
    uint32_t a;
    asm("{ .reg .u64 t; cvta.to.shared.u64 t, %1; cvt.u32.u64 %0, t; }" : "=r"(a) : "l"(p));
    return a;
}
__device__ __forceinline__ void mma16(float* c, const unsigned* a, const unsigned* b) {
    asm volatile(
        "mma.sync.aligned.m16n8k16.row.col.f32.f16.f16.f32 "
        "{%0,%1,%2,%3}, {%4,%5,%6,%7}, {%8,%9}, {%0,%1,%2,%3};\n"
        : "+f"(c[0]), "+f"(c[1]), "+f"(c[2]), "+f"(c[3])
        : "r"(a[0]), "r"(a[1]), "r"(a[2]), "r"(a[3]),
          "r"(b[0]), "r"(b[1]));
}
#define LDSM4(r0, r1, r2, r3, addr)                                          \
    asm volatile("ldmatrix.sync.aligned.m8n8.x4.shared.b16 {%0,%1,%2,%3}, [%4];" \
                 : "=r"(r0), "=r"(r1), "=r"(r2), "=r"(r3) : "r"(addr))
#define CP16(sp, gp) asm volatile("cp.async.cg.shared.global [%0], [%1], 16;" :: "r"(sp), "l"(gp) : "memory")

// ---------------------------------------------------------------------------
// fp32 -> fp16 (rn) conversion pre-pass
// ---------------------------------------------------------------------------
__global__ void __launch_bounds__(256) cvt_f16(const float4* __restrict__ s,
                                               uint2* __restrict__ d, int n4) {
    int i = blockIdx.x * 256 + threadIdx.x;
    if (i < n4) {
        float4 v = s[i];
        __half2 h0 = __floats2half2_rn(v.x, v.y);
        __half2 h1 = __floats2half2_rn(v.z, v.w);
        uint2 o;
        o.x = *(unsigned*)&h0;
        o.y = *(unsigned*)&h1;
        d[i] = o;
    }
}

struct CvtBatch { const float4* s[5]; uint2* d[5]; };
__global__ void __launch_bounds__(256) cvt_f16_w(CvtBatch cb) {
    const int w = blockIdx.y;
    const float4* s = cb.s[w];
    uint2*        d = cb.d[w];
    int i = blockIdx.x * 256 + threadIdx.x;
    float4 v = s[i];
    __half2 h0 = __floats2half2_rn(v.x, v.y);
    __half2 h1 = __floats2half2_rn(v.z, v.w);
    uint2 o;
    o.x = *(unsigned*)&h0;
    o.y = *(unsigned*)&h1;
    d[i] = o;
}

// ---------------------------------------------------------------------------
// FP16 GEMM, mma.sync m16n8k16 with LDSM fragment loads:
//   out[p, n] = act( sum_k A[p,k] * W[n,k] + bias[n] )   A,W fp16, acc fp32.
//   CTA 128x128, 4 warps (warp tile 64x64), KTILE=64 halves, 3-stage cp.async.
//   Fragments via ldmatrix.x4: 8 LDSM per k16-step instead of 32 scalar LDS.
// ---------------------------------------------------------------------------
#define KT2   64                 // k halves per tile (128 B per row)
#define AST   36                 // smem row stride in words (32 data + 4 pad)
#define TILE_WORDS (128 * AST)   // words per matrix per stage (4608)
#define STAGE_BYTES (2 * TILE_WORDS * 4)   // A+B per stage = 36864
#define NSTAGE 3
#define SMEM_SZ (NSTAGE * STAGE_BYTES + 640)  // 111232 B; 2 CTAs/SM

struct GemmBatch {
    const __half* W[4];
    const float*  bias[4];
    float*        out[4];
    int           act[4];
    int           tmajor;
};

__device__ __forceinline__ void load_tile2(const __half* Ab, const __half* Wb,
                                           int kt, uint32_t abase, uint32_t bbase,
                                           int tid) {
    const int k0  = kt * KT2;
    const int row = tid >> 3;            // 0..15 base rows
    const int col = tid & 7;             // 16B chunk (8 halves) in row
    #pragma unroll
    for (int i = 0; i < 8; i++) {        // A: 128 rows x 8 chunks
        const int r = i * 16 + row;
        CP16(abase + r * (AST * 4) + col * 16,
             Ab + (size_t)r * Mm + k0 + col * 8);
    }
    #pragma unroll
    for (int i = 0; i < 8; i++) {        // B: 128 rows x 8 chunks
        const int r = i * 16 + row;
        CP16(bbase + r * (AST * 4) + col * 16,
             Wb + (size_t)r * Mm + k0 + col * 8);
    }
    asm volatile("cp.async.commit_group;" ::: "memory");
}

__global__ void __launch_bounds__(128, 2) gemm_f16(
    const __half* __restrict__ A, GemmBatch gb)
{
    extern __shared__ char smem[];
    float* biasS = (float*)(smem + NSTAGE * STAGE_BYTES);
    const uint32_t sbase = smem_u32(smem);

    const int pt = blockIdx.x;
    const int nt = blockIdx.y;
    const int z  = blockIdx.z;

    const __half* W    = gb.W[z];
    const float*  bias = gb.bias[z];
    float*        out  = gb.out[z];
    const int     act  = gb.act[z];
    const int  tmajor  = gb.tmajor;

    const int tid  = threadIdx.x;
    const int lane = tid & 31;
    const int wid  = tid >> 5;
    const int wp   = wid & 1;     // warp M half (2 x 64)
    const int wn   = wid >> 1;    // warp N half (2 x 64)
    const int lq   = lane >> 2;   // 0..7 (epilogue row group)
    const int lr   = lane & 3;    // 0..3 (epilogue col group)

    biasS[tid] = bias ? bias[nt * 128 + tid] : 0.0f;

    // ldmatrix per-thread address components (word offsets within a stage):
    //   A x4 tiles (m16k16): rows m_base + (lane&15), k-half word +4*(lane>>4)
    //   B x4 = two n8k16 fragments: row n_base + (lane>>4)*8 + (lane&7),
    //                               k-half word +4*((lane>>3)&1)
    const int aoff0 = (wp * 64 + (lane & 15)) * AST + (lane >> 4) * 4;
    const int boff0 = (wn * 64 + (lane >> 4) * 8 + (lane & 7)) * AST
                      + ((lane >> 3) & 1) * 4;

    const __half* Ab = A + (size_t)pt * 128 * Mm;
    const __half* Wb = W + (size_t)nt * 128 * Mm;

    float acc[4][8][4];
    #pragma unroll
    for (int i = 0; i < 4; i++)
        #pragma unroll
        for (int j = 0; j < 8; j++)
            #pragma unroll
            for (int k = 0; k < 4; k++) acc[i][j][k] = 0.0f;

    // prologue: fill 2 of the 3 stages
    load_tile2(Ab, Wb, 0, sbase,               sbase + TILE_WORDS * 4,               tid);
    load_tile2(Ab, Wb, 1, sbase + STAGE_BYTES, sbase + STAGE_BYTES + TILE_WORDS * 4, tid);

    const int NTK = Mm / KT2;     // 16
    int stage = 0;
    for (int kt = 0; kt < NTK; kt++) {
        if (kt < NTK - 1)
            asm volatile("cp.async.wait_group 1;" ::: "memory");
        else
            asm volatile("cp.async.wait_group 0;" ::: "memory");
        __syncthreads();

        if (kt + 2 < NTK) {
            const int ns = (stage + 2) % NSTAGE;
            load_tile2(Ab, Wb, kt + 2,
                       sbase + ns * STAGE_BYTES,
                       sbase + ns * STAGE_BYTES + TILE_WORDS * 4, tid);
        }

        const uint32_t sa = sbase + stage * STAGE_BYTES;
        const uint32_t sb = sa + TILE_WORDS * 4;
        #pragma unroll
        for (int ks = 0; ks < 4; ks++) {
            unsigned af[4][4], bf[8][2];
            #pragma unroll
            for (int mi = 0; mi < 4; mi++) {
                const uint32_t addr = sa + 4 * (aoff0 + mi * 16 * AST + ks * 8);
                LDSM4(af[mi][0], af[mi][1], af[mi][2], af[mi][3], addr);
            }
            #pragma unroll
            for (int nj = 0; nj < 4; nj++) {   // two n8 fragments per LDSM
                const uint32_t addr = sb + 4 * (boff0 + nj * 16 * AST + ks * 8);
                LDSM4(bf[2 * nj][0], bf[2 * nj][1],
                      bf[2 * nj + 1][0], bf[2 * nj + 1][1], addr);
            }
            #pragma unroll
            for (int mi = 0; mi < 4; mi++)
                #pragma unroll
                for (int ni = 0; ni < 8; ni++)
                    mma16(acc[mi][ni], af[mi], bf[ni]);
        }
        stage = (stage + 1) % NSTAGE;
    }

    // epilogue: direct float2 stores
    #pragma unroll
    for (int mi = 0; mi < 4; mi++) {
        #pragma unroll
        for (int half = 0; half < 2; half++) {
            const int p = pt * 128 + wp * 64 + mi * 16 + lq + half * 8;
            size_t obase;
            if (tmajor) {
                const int bb = p >> 11;
                const int t  = p & 2047;
                obase = (size_t)t * BM + (size_t)bb * Mm;
            } else {
                obase = (size_t)p * Mm;
            }
            #pragma unroll
            for (int ni = 0; ni < 8; ni++) {
                const int cloc = wn * 64 + ni * 8 + lr * 2;
                const int col  = nt * 128 + cloc;
                float v0 = acc[mi][ni][half * 2 + 0] + biasS[cloc];
                float v1 = acc[mi][ni][half * 2 + 1] + biasS[cloc + 1];
                if (act) { v0 = sigmf(v0); v1 = sigmf(v1); }
                *(float2*)(out + obase + col) = make_float2(v0, v1);
            }
        }
    }
}

// ---------------------------------------------------------------------------
// Chunked linear scan (scalar lanes):  h_t = h_{t-1} * r_t + zi_t * sg_t
// ---------------------------------------------------------------------------
__global__ void __launch_bounds__(256) scan_pass1() {
    const int idx = blockIdx.x * 256 + threadIdx.x;  // NC*BM = 262144
    const int c   = idx >> 13;
    const int bm  = idx & 8191;
    int base = c * CL * BM + bm;
    float h = 0.0f, A = 1.0f;
    #pragma unroll 8
    for (int i = 0; i < CL; i++) {
        const float r  = g_r[base];
        const float xi = g_zi[base] * g_sg[base];
        h = h * r + xi;
        A *= r;
        base += BM;
    }
    g_cA[idx] = A;
    g_cB[idx] = h;
}

__global__ void __launch_bounds__(256) scan_mid(const float* __restrict__ mem) {
    const int bm = blockIdx.x * 256 + threadIdx.x;   // 8192
    float h = mem[bm];
    #pragma unroll
    for (int c = 0; c < NC; c++) {
        g_h0[c * BM + bm] = h;
        h = g_cB[c * BM + bm] + g_cA[c * BM + bm] * h;
    }
}

__global__ void __launch_bounds__(256) scan_pass2(float* __restrict__ memout) {
    const int idx = blockIdx.x * 256 + threadIdx.x;
    const int c   = idx >> 13;
    const int bm  = idx & 8191;
    const int bb  = bm >> 10;
    const int m   = bm & 1023;
    float h = g_h0[idx];
    int base = c * CL * BM + bm;
    size_t ybase = (size_t)bb * Tt * Mm + (size_t)(c * CL) * Mm + m;
    #pragma unroll 8
    for (int i = 0; i < CL; i++) {
        const float r  = g_r[base];
        const float xi = g_zi[base] * g_sg[base];
        h = h * r + xi;
        const float ss = h / (1.0f + fabsf(h));
        g_y[ybase] = __float2half_rn(ss * g_og[base]);   // fp16 for final GEMM
        base  += BM;
        ybase += Mm;
    }
    if (c == NC - 1 && memout) memout[bm] = h;   // mem_out stays fp32-exact
}

// ---------------------------------------------------------------------------
// Launch
// ---------------------------------------------------------------------------
extern "C" void kernel_launch(void* const* d_in, const int* in_sizes, int n_in,
                              void* d_out, int out_size) {
    (void)in_sizes; (void)n_in;
    const float* x     = (const float*)d_in[0];
    const float* mem   = (const float*)d_in[1];
    const float* wr_w  = (const float*)d_in[2];
    const float* wr_b  = (const float*)d_in[3];
    const float* wi_w  = (const float*)d_in[4];
    const float* wig_w = (const float*)d_in[5];
    const float* wig_b = (const float*)d_in[6];
    const float* wog_w = (const float*)d_in[7];
    const float* wog_b = (const float*)d_in[8];
    const float* wo_w  = (const float*)d_in[9];
    float* outp = (float*)d_out;

    float  *p_r, *p_og, *p_zi, *p_sg;
    __half *p_y, *p_xh, *p_w0, *p_w1, *p_w2, *p_w3, *p_w4;
    cudaGetSymbolAddress((void**)&p_r,  g_r);
    cudaGetSymbolAddress((void**)&p_og, g_og);
    cudaGetSymbolAddress((void**)&p_zi, g_zi);
    cudaGetSymbolAddress((void**)&p_sg, g_sg);
    cudaGetSymbolAddress((void**)&p_y,  g_y);
    cudaGetSymbolAddress((void**)&p_xh, g_xh);
    cudaGetSymbolAddress((void**)&p_w0, g_w0);
    cudaGetSymbolAddress((void**)&p_w1, g_w1);
    cudaGetSymbolAddress((void**)&p_w2, g_w2);
    cudaGetSymbolAddress((void**)&p_w3, g_w3);
    cudaGetSymbolAddress((void**)&p_w4, g_w4);

    static bool attr_done = false;
    if (!attr_done) {
        cudaFuncSetAttribute(gemm_f16, cudaFuncAttributeMaxDynamicSharedMemorySize, SMEM_SZ);
        attr_done = true;
    }

    // rn rounding to fp16
    const int nx4 = (PROWS * Mm) / 4;
    const int nw4 = (Mm * Mm) / 4;
    cvt_f16<<<(nx4 + 255) / 256, 256>>>((const float4*)x, (uint2*)p_xh, nx4);
    {
        CvtBatch cb;
        cb.s[0] = (const float4*)wr_w;  cb.d[0] = (uint2*)p_w0;
        cb.s[1] = (const float4*)wog_w; cb.d[1] = (uint2*)p_w1;
        cb.s[2] = (const float4*)wi_w;  cb.d[2] = (uint2*)p_w2;
        cb.s[3] = (const float4*)wig_w; cb.d[3] = (uint2*)p_w3;
        cb.s[4] = (const float4*)wo_w;  cb.d[4] = (uint2*)p_w4;
        cvt_f16_w<<<dim3(nw4 / 256, 5), 256>>>(cb);
    }

    // four input projections, one launch (grid.z = 4)
    {
        GemmBatch gb;
        gb.W[0] = p_w0; gb.bias[0] = wr_b;    gb.out[0] = p_r;  gb.act[0] = 1;
        gb.W[1] = p_w1; gb.bias[1] = wog_b;   gb.out[1] = p_og; gb.act[1] = 1;
        gb.W[2] = p_w2; gb.bias[2] = nullptr; gb.out[2] = p_zi; gb.act[2] = 0;
        gb.W[3] = p_w3; gb.bias[3] = wig_b;   gb.out[3] = p_sg; gb.act[3] = 1;
        gb.tmajor = 1;
        dim3 grid(PROWS / 128, Mm / 128, 4);
        gemm_f16<<<grid, 128, SMEM_SZ>>>(p_xh, gb);
    }

    // chunked scan (scalar lanes)
    scan_pass1<<<(NC * BM) / 256, 256>>>();
    scan_mid<<<BM / 256, 256>>>(mem);
    float* memout = (out_size >= PROWS * Mm + BM) ? (outp + (size_t)PROWS * Mm)
                                                  : nullptr;
    scan_pass2<<<(NC * BM) / 256, 256>>>(memout);

    // output projection straight to d_out (p-major)
    {
        GemmBatch gb;
        gb.W[0] = p_w4; gb.bias[0] = nullptr; gb.out[0] = outp; gb.act[0] = 0;
        gb.W[1] = gb.W[2] = gb.W[3] = nullptr;
        gb.bias[1] = gb.bias[2] = gb.bias[3] = nullptr;
        gb.out[1] = gb.out[2] = gb.out[3] = nullptr;
        gb.act[1] = gb.act[2] = gb.act[3] = 0;
        gb.tmajor = 0;
        dim3 grid(PROWS / 128, Mm / 128, 1);
        gemm_f16<<<grid, 128, SMEM_SZ>>>(p_y, gb);
    }
}

// round 16
// speedup vs baseline: 1.1511x; 1.1511x over previous
#include <cuda_runtime.h>
#include <cuda_fp16.h>
#include <cstdint>
#include <cstddef>

// ---------------------------------------------------------------------------
// Problem constants
// ---------------------------------------------------------------------------
#define Bb     8
#define Tt     2048
#define Mm     1024
#define PROWS  (Bb * Tt)      // 16384
#define CL     64             // scan chunk length
#define NC     (Tt / CL)      // 32 chunks
#define BM     (Bb * Mm)      // 8192

// ---------------------------------------------------------------------------
// Scratch (static __device__ arrays; runtime allocation is forbidden)
// r stays fp32 (enters long products in the recurrence); zi/sg/og fp16
// (enter additively / once, fp16 rounding stays ~2.4e-4 relative).
// ---------------------------------------------------------------------------
__device__ float  g_r [PROWS * Mm];   // sigmoid(x@wr^T + b)   (t-major, f32)
__device__ __half g_og[PROWS * Mm];   // sigmoid(x@wog^T + b)  (t-major, f16)
__device__ __half g_zi[PROWS * Mm];   // raw x@wi^T            (t-major, f16)
__device__ __half g_sg[PROWS * Mm];   // sigmoid(x@wig^T + b)  (t-major, f16)
__device__ __half g_y [PROWS * Mm];   // softsign(h)*og, p-major, fp16
__device__ __half g_xh[PROWS * Mm];   // x rounded to fp16 (rn)
__device__ __half g_w0[Mm * Mm];      // wr  fp16
__device__ __half g_w1[Mm * Mm];      // wog fp16
__device__ __half g_w2[Mm * Mm];      // wi  fp16
__device__ __half g_w3[Mm * Mm];      // wig fp16
__device__ __half g_w4[Mm * Mm];      // wo  fp16
__device__ float  g_cA[NC * BM];
__device__ float  g_cB[NC * BM];
__device__ float  g_h0[NC * BM];

// ---------------------------------------------------------------------------
// Helpers
// ---------------------------------------------------------------------------
__device__ __forceinline__ float sigmf(float x) {
    return 1.0f / (1.0f + __expf(-x));
}
__device__ __forceinline__ uint32_t smem_u32(const void* p) {
    uint32_t a;
    asm("{ .reg .u64 t; cvta.to.shared.u64 t, %1; cvt.u32.u64 %0, t; }" : "=r"(a) : "l"(p));
    return a;
}
__device__ __forceinline__ void mma16(float* c, const unsigned* a, const unsigned* b) {
    asm volatile(
        "mma.sync.aligned.m16n8k16.row.col.f32.f16.f16.f32 "
        "{%0,%1,%2,%3}, {%4,%5,%6,%7}, {%8,%9}, {%0,%1,%2,%3};\n"
        : "+f"(c[0]), "+f"(c[1]), "+f"(c[2]), "+f"(c[3])
        : "r"(a[0]), "r"(a[1]), "r"(a[2]), "r"(a[3]),
          "r"(b[0]), "r"(b[1]));
}
#define LDSM4(r0, r1, r2, r3, addr)                                          \
    asm volatile("ldmatrix.sync.aligned.m8n8.x4.shared.b16 {%0,%1,%2,%3}, [%4];" \
                 : "=r"(r0), "=r"(r1), "=r"(r2), "=r"(r3) : "r"(addr))
#define CP16(sp, gp) asm volatile("cp.async.cg.shared.global [%0], [%1], 16;" :: "r"(sp), "l"(gp) : "memory")

// ---------------------------------------------------------------------------
// fp32 -> fp16 (rn) conversion pre-pass
// ---------------------------------------------------------------------------
__global__ void __launch_bounds__(256) cvt_f16(const float4* __restrict__ s,
                                               uint2* __restrict__ d, int n4) {
    int i = blockIdx.x * 256 + threadIdx.x;
    if (i < n4) {
        float4 v = s[i];
        __half2 h0 = __floats2half2_rn(v.x, v.y);
        __half2 h1 = __floats2half2_rn(v.z, v.w);
        uint2 o;
        o.x = *(unsigned*)&h0;
        o.y = *(unsigned*)&h1;
        d[i] = o;
    }
}

struct CvtBatch { const float4* s[5]; uint2* d[5]; };
__global__ void __launch_bounds__(256) cvt_f16_w(CvtBatch cb) {
    const int w = blockIdx.y;
    const float4* s = cb.s[w];
    uint2*        d = cb.d[w];
    int i = blockIdx.x * 256 + threadIdx.x;
    float4 v = s[i];
    __half2 h0 = __floats2half2_rn(v.x, v.y);
    __half2 h1 = __floats2half2_rn(v.z, v.w);
    uint2 o;
    o.x = *(unsigned*)&h0;
    o.y = *(unsigned*)&h1;
    d[i] = o;
}

// ---------------------------------------------------------------------------
// FP16 GEMM, mma.sync m16n8k16 + LDSM:
//   out[p, n] = act( sum_k A[p,k] * W[n,k] + bias[n] )   A,W fp16, acc fp32.
//   CTA 128x128, 4 warps (warp tile 64x64), KTILE=64 halves.
//   TWO-stage pipeline (R7 form) -> smem 74.4 KB -> 3 CTAs/SM (12 warps):
//   occupancy is the remaining untested axis for the ~45%-of-pipe GEMM.
//   Per-z output dtype selectable (fp32 or fp16).
// ---------------------------------------------------------------------------
#define KT2   64                 // k halves per tile (128 B per row)
#define AST   36                 // smem row stride in words (32 data + 4 pad)
#define TILE_WORDS (128 * AST)   // words per matrix per stage (4608)
#define STAGE_BYTES (2 * TILE_WORDS * 4)   // A+B per stage = 36864
#define NSTAGE 2
#define SMEM_SZ (NSTAGE * STAGE_BYTES + 640)  // 74368 B; 3 CTAs/SM

struct GemmBatch {
    const __half* W[4];
    const float*  bias[4];
    void*         out[4];
    int           act[4];
    int           ohalf[4];   // 1 -> output fp16, 0 -> fp32
    int           tmajor;
};

__device__ __forceinline__ void load_tile2(const __half* Ab, const __half* Wb,
                                           int kt, uint32_t abase, uint32_t bbase,
                                           int tid) {
    const int k0  = kt * KT2;
    const int row = tid >> 3;            // 0..15 base rows
    const int col = tid & 7;             // 16B chunk (8 halves) in row
    #pragma unroll
    for (int i = 0; i < 8; i++) {        // A: 128 rows x 8 chunks
        const int r = i * 16 + row;
        CP16(abase + r * (AST * 4) + col * 16,
             Ab + (size_t)r * Mm + k0 + col * 8);
    }
    #pragma unroll
    for (int i = 0; i < 8; i++) {        // B: 128 rows x 8 chunks
        const int r = i * 16 + row;
        CP16(bbase + r * (AST * 4) + col * 16,
             Wb + (size_t)r * Mm + k0 + col * 8);
    }
    asm volatile("cp.async.commit_group;" ::: "memory");
}

__global__ void __launch_bounds__(128, 3) gemm_f16(
    const __half* __restrict__ A, GemmBatch gb)
{
    extern __shared__ char smem[];
    float* biasS = (float*)(smem + NSTAGE * STAGE_BYTES);
    const uint32_t sbase = smem_u32(smem);

    const int pt = blockIdx.x;
    const int nt = blockIdx.y;
    const int z  = blockIdx.z;

    const __half* W    = gb.W[z];
    const float*  bias = gb.bias[z];
    void*         outv = gb.out[z];
    const int     act  = gb.act[z];
    const int   ohalf  = gb.ohalf[z];
    const int  tmajor  = gb.tmajor;

    const int tid  = threadIdx.x;
    const int lane = tid & 31;
    const int wid  = tid >> 5;
    const int wp   = wid & 1;     // warp M half (2 x 64)
    const int wn   = wid >> 1;    // warp N half (2 x 64)
    const int lq   = lane >> 2;   // 0..7 (epilogue row group)
    const int lr   = lane & 3;    // 0..3 (epilogue col group)

    biasS[tid] = bias ? bias[nt * 128 + tid] : 0.0f;

    const int aoff0 = (wp * 64 + (lane & 15)) * AST + (lane >> 4) * 4;
    const int boff0 = (wn * 64 + (lane >> 4) * 8 + (lane & 7)) * AST
                      + ((lane >> 3) & 1) * 4;

    const __half* Ab = A + (size_t)pt * 128 * Mm;
    const __half* Wb = W + (size_t)nt * 128 * Mm;

    float acc[4][8][4];
    #pragma unroll
    for (int i = 0; i < 4; i++)
        #pragma unroll
        for (int j = 0; j < 8; j++)
            #pragma unroll
            for (int k = 0; k < 4; k++) acc[i][j][k] = 0.0f;

    load_tile2(Ab, Wb, 0, sbase, sbase + TILE_WORDS * 4, tid);

    const int NTK = Mm / KT2;     // 16
    for (int kt = 0; kt < NTK; kt++) {
        const int buf = kt & 1;
        asm volatile("cp.async.wait_group 0;" ::: "memory");
        __syncthreads();
        if (kt + 1 < NTK)
            load_tile2(Ab, Wb, kt + 1,
                       sbase + (buf ^ 1) * STAGE_BYTES,
                       sbase + (buf ^ 1) * STAGE_BYTES + TILE_WORDS * 4, tid);

        const uint32_t sa = sbase + buf * STAGE_BYTES;
        const uint32_t sb = sa + TILE_WORDS * 4;
        #pragma unroll
        for (int ks = 0; ks < 4; ks++) {
            unsigned af[4][4], bf[8][2];
            #pragma unroll
            for (int mi = 0; mi < 4; mi++) {
                const uint32_t addr = sa + 4 * (aoff0 + mi * 16 * AST + ks * 8);
                LDSM4(af[mi][0], af[mi][1], af[mi][2], af[mi][3], addr);
            }
            #pragma unroll
            for (int nj = 0; nj < 4; nj++) {
                const uint32_t addr = sb + 4 * (boff0 + nj * 16 * AST + ks * 8);
                LDSM4(bf[2 * nj][0], bf[2 * nj][1],
                      bf[2 * nj + 1][0], bf[2 * nj + 1][1], addr);
            }
            #pragma unroll
            for (int mi = 0; mi < 4; mi++)
                #pragma unroll
                for (int ni = 0; ni < 8; ni++)
                    mma16(acc[mi][ni], af[mi], bf[ni]);
        }
    }

    // epilogue
    #pragma unroll
    for (int mi = 0; mi < 4; mi++) {
        #pragma unroll
        for (int half = 0; half < 2; half++) {
            const int p = pt * 128 + wp * 64 + mi * 16 + lq + half * 8;
            size_t obase;
            if (tmajor) {
                const int bb = p >> 11;
                const int t  = p & 2047;
                obase = (size_t)t * BM + (size_t)bb * Mm;
            } else {
                obase = (size_t)p * Mm;
            }
            #pragma unroll
            for (int ni = 0; ni < 8; ni++) {
                const int cloc = wn * 64 + ni * 8 + lr * 2;
                const int col  = nt * 128 + cloc;
                float v0 = acc[mi][ni][half * 2 + 0] + biasS[cloc];
                float v1 = acc[mi][ni][half * 2 + 1] + biasS[cloc + 1];
                if (act) { v0 = sigmf(v0); v1 = sigmf(v1); }
                if (ohalf) {
                    __half2 h = __floats2half2_rn(v0, v1);
                    *(__half2*)((__half*)outv + obase + col) = h;
                } else {
                    *(float2*)((float*)outv + obase + col) = make_float2(v0, v1);
                }
            }
        }
    }
}

// ---------------------------------------------------------------------------
// Chunked linear scan (scalar lanes):  h_t = h_{t-1} * r_t + zi_t * sg_t
// r fp32; zi/sg/og fp16.
// ---------------------------------------------------------------------------
__global__ void __launch_bounds__(256) scan_pass1() {
    const int idx = blockIdx.x * 256 + threadIdx.x;  // NC*BM = 262144
    const int c   = idx >> 13;
    const int bm  = idx & 8191;
    int base = c * CL * BM + bm;
    float h = 0.0f, A = 1.0f;
    #pragma unroll 8
    for (int i = 0; i < CL; i++) {
        const float r  = g_r[base];
        const float xi = __half2float(g_zi[base]) * __half2float(g_sg[base]);
        h = h * r + xi;
        A *= r;
        base += BM;
    }
    g_cA[idx] = A;
    g_cB[idx] = h;
}

__global__ void __launch_bounds__(256) scan_mid(const float* __restrict__ mem) {
    const int bm = blockIdx.x * 256 + threadIdx.x;   // 8192
    float h = mem[bm];
    #pragma unroll
    for (int c = 0; c < NC; c++) {
        g_h0[c * BM + bm] = h;
        h = g_cB[c * BM + bm] + g_cA[c * BM + bm] * h;
    }
}

__global__ void __launch_bounds__(256) scan_pass2(float* __restrict__ memout) {
    const int idx = blockIdx.x * 256 + threadIdx.x;
    const int c   = idx >> 13;
    const int bm  = idx & 8191;
    const int bb  = bm >> 10;
    const int m   = bm & 1023;
    float h = g_h0[idx];
    int base = c * CL * BM + bm;
    size_t ybase = (size_t)bb * Tt * Mm + (size_t)(c * CL) * Mm + m;
    #pragma unroll 8
    for (int i = 0; i < CL; i++) {
        const float r  = g_r[base];
        const float xi = __half2float(g_zi[base]) * __half2float(g_sg[base]);
        h = h * r + xi;
        const float ss = h / (1.0f + fabsf(h));
        g_y[ybase] = __float2half_rn(ss * __half2float(g_og[base]));
        base  += BM;
        ybase += Mm;
    }
    if (c == NC - 1 && memout) memout[bm] = h;   // mem_out stays fp32-exact
}

// ---------------------------------------------------------------------------
// Launch
// ---------------------------------------------------------------------------
extern "C" void kernel_launch(void* const* d_in, const int* in_sizes, int n_in,
                              void* d_out, int out_size) {
    (void)in_sizes; (void)n_in;
    const float* x     = (const float*)d_in[0];
    const float* mem   = (const float*)d_in[1];
    const float* wr_w  = (const float*)d_in[2];
    const float* wr_b  = (const float*)d_in[3];
    const float* wi_w  = (const float*)d_in[4];
    const float* wig_w = (const float*)d_in[5];
    const float* wig_b = (const float*)d_in[6];
    const float* wog_w = (const float*)d_in[7];
    const float* wog_b = (const float*)d_in[8];
    const float* wo_w  = (const float*)d_in[9];
    float* outp = (float*)d_out;

    float  *p_r;
    __half *p_og, *p_zi, *p_sg, *p_y, *p_xh, *p_w0, *p_w1, *p_w2, *p_w3, *p_w4;
    cudaGetSymbolAddress((void**)&p_r,  g_r);
    cudaGetSymbolAddress((void**)&p_og, g_og);
    cudaGetSymbolAddress((void**)&p_zi, g_zi);
    cudaGetSymbolAddress((void**)&p_sg, g_sg);
    cudaGetSymbolAddress((void**)&p_y,  g_y);
    cudaGetSymbolAddress((void**)&p_xh, g_xh);
    cudaGetSymbolAddress((void**)&p_w0, g_w0);
    cudaGetSymbolAddress((void**)&p_w1, g_w1);
    cudaGetSymbolAddress((void**)&p_w2, g_w2);
    cudaGetSymbolAddress((void**)&p_w3, g_w3);
    cudaGetSymbolAddress((void**)&p_w4, g_w4);

    static bool attr_done = false;
    if (!attr_done) {
        cudaFuncSetAttribute(gemm_f16, cudaFuncAttributeMaxDynamicSharedMemorySize, SMEM_SZ);
        attr_done = true;
    }

    // rn rounding to fp16
    const int nx4 = (PROWS * Mm) / 4;
    const int nw4 = (Mm * Mm) / 4;
    cvt_f16<<<(nx4 + 255) / 256, 256>>>((const float4*)x, (uint2*)p_xh, nx4);
    {
        CvtBatch cb;
        cb.s[0] = (const float4*)wr_w;  cb.d[0] = (uint2*)p_w0;
        cb.s[1] = (const float4*)wog_w; cb.d[1] = (uint2*)p_w1;
        cb.s[2] = (const float4*)wi_w;  cb.d[2] = (uint2*)p_w2;
        cb.s[3] = (const float4*)wig_w; cb.d[3] = (uint2*)p_w3;
        cb.s[4] = (const float4*)wo_w;  cb.d[4] = (uint2*)p_w4;
        cvt_f16_w<<<dim3(nw4 / 256, 5), 256>>>(cb);
    }

    // four input projections, one launch (grid.z = 4)
    {
        GemmBatch gb;
        gb.W[0] = p_w0; gb.bias[0] = wr_b;    gb.out[0] = p_r;  gb.act[0] = 1; gb.ohalf[0] = 0;
        gb.W[1] = p_w1; gb.bias[1] = wog_b;   gb.out[1] = p_og; gb.act[1] = 1; gb.ohalf[1] = 1;
        gb.W[2] = p_w2; gb.bias[2] = nullptr; gb.out[2] = p_zi; gb.act[2] = 0; gb.ohalf[2] = 1;
        gb.W[3] = p_w3; gb.bias[3] = wig_b;   gb.out[3] = p_sg; gb.act[3] = 1; gb.ohalf[3] = 1;
        gb.tmajor = 1;
        dim3 grid(PROWS / 128, Mm / 128, 4);
        gemm_f16<<<grid, 128, SMEM_SZ>>>(p_xh, gb);
    }

    // chunked scan (scalar lanes)
    scan_pass1<<<(NC * BM) / 256, 256>>>();
    scan_mid<<<BM / 256, 256>>>(mem);
    float* memout = (out_size >= PROWS * Mm + BM) ? (outp + (size_t)PROWS * Mm)
                                                  : nullptr;
    scan_pass2<<<(NC * BM) / 256, 256>>>(memout);

    // output projection straight to d_out (p-major, fp32)
    {
        GemmBatch gb;
        gb.W[0] = p_w4; gb.bias[0] = nullptr; gb.out[0] = outp; gb.act[0] = 0; gb.ohalf[0] = 0;
        gb.W[1] = gb.W[2] = gb.W[3] = nullptr;
        gb.bias[1] = gb.bias[2] = gb.bias[3] = nullptr;
        gb.out[1] = gb.out[2] = gb.out[3] = nullptr;
        gb.act[1] = gb.act[2] = gb.act[3] = 0;
        gb.ohalf[1] = gb.ohalf[2] = gb.ohalf[3] = 0;
        gb.tmajor = 0;
        dim3 grid(PROWS / 128, Mm / 128, 1);
        gemm_f16<<<grid, 128, SMEM_SZ>>>(p_y, gb);
    }
}